// round 10
// baseline (speedup 1.0000x reference)
#include <cuda_runtime.h>
#include <cstdint>

// Problem constants (fixed by the dataset)
#define B 8
#define N 2048
#define IN_F 512
#define OUT_F 128
#define RPW 2
#define TR 16

// Scratch (allocation-free rule: __device__ globals), 16B-aligned for float4
__device__ __align__(16) float g_w1[IN_F];
__device__ __align__(16) float g_w2[IN_F];
__device__ __align__(16) float g_x8[B * N];   // 0.125 * (emb1[b,i,:] . w1)
__device__ __align__(16) float g_y8[B * N];   // 0.125 * (emb1[b,i,:] . w2)
__device__ __align__(16) float g_xm[B * N];   // act ? x8 : -1e30
__device__ __align__(16) float g_ym[B * N];   // act ? y8 : -1e30
__device__ float g_scale[B];

__device__ __forceinline__ float tanh_fast(float x) {
    float r;
    asm("tanh.approx.f32 %0, %1;" : "=f"(r) : "f"(x));
    return r;
}

// PDL primitives. wait pairs with the immediately-preceding kernel's trigger.
__device__ __forceinline__ void pdl_wait() {
    asm volatile("griddepcontrol.wait;" ::: "memory");
}
__device__ __forceinline__ void pdl_trigger() {
    asm volatile("griddepcontrol.launch_dependents;" ::: "memory");
}

// K1: w1 = W^T a1, w2 = W^T a2.  W is [OUT_F, IN_F] row-major.
__global__ void __launch_bounds__(256) k_wproj(const float* __restrict__ W,
                                               const float* __restrict__ a1,
                                               const float* __restrict__ a2) {
    int lane = threadIdx.x & 31;
    int oq   = threadIdx.x >> 5;                 // 0..7
    int f    = blockIdx.x * 32 + lane;           // 0..511
    float s1 = 0.f, s2 = 0.f;
#pragma unroll
    for (int o = oq * 16; o < oq * 16 + 16; o++) {
        float w = __ldg(W + (size_t)o * IN_F + f);
        s1 = fmaf(w, __ldg(a1 + o), s1);
        s2 = fmaf(w, __ldg(a2 + o), s2);
    }
    __shared__ float p1[256], p2[256];
    p1[threadIdx.x] = s1;
    p2[threadIdx.x] = s2;
    __syncthreads();
    if (threadIdx.x < 32) {
        float r1 = 0.f, r2 = 0.f;
#pragma unroll
        for (int c = 0; c < 8; c++) {
            r1 += p1[lane + 32 * c];
            r2 += p2[lane + 32 * c];
        }
        g_w1[f] = r1;
        g_w2[f] = r2;
    }
    pdl_trigger();   // data-complete trigger: xy consumes w1/w2
}

// K2: per-warp dual dot products, 2 rows per warp, w1/w2 in registers.
// Stored pre-scaled by 0.125 (exact pow2).
__global__ void __launch_bounds__(256) k_xy(const float* __restrict__ emb) {
    pdl_wait();
    int warp = (blockIdx.x * blockDim.x + threadIdx.x) >> 5;
    int lane = threadIdx.x & 31;
    int row0 = warp * RPW;                       // 8192 warps cover 16384 rows

    const float4* w1 = reinterpret_cast<const float4*>(g_w1);
    const float4* w2 = reinterpret_cast<const float4*>(g_w2);
    float4 W1[4], W2[4];
#pragma unroll
    for (int k = 0; k < 4; k++) {
        W1[k] = w1[lane + 32 * k];
        W2[k] = w2[lane + 32 * k];
    }

    float s1[RPW] = {0.f, 0.f}, s2[RPW] = {0.f, 0.f};
#pragma unroll
    for (int r = 0; r < RPW; r++) {
        const float4* row = reinterpret_cast<const float4*>(emb + (size_t)(row0 + r) * IN_F);
#pragma unroll
        for (int k = 0; k < 4; k++) {
            float4 e = row[lane + 32 * k];
            s1[r] = fmaf(e.x, W1[k].x, fmaf(e.y, W1[k].y, fmaf(e.z, W1[k].z, fmaf(e.w, W1[k].w, s1[r]))));
            s2[r] = fmaf(e.x, W2[k].x, fmaf(e.y, W2[k].y, fmaf(e.z, W2[k].z, fmaf(e.w, W2[k].w, s2[r]))));
        }
    }
#pragma unroll
    for (int off = 16; off; off >>= 1) {
#pragma unroll
        for (int r = 0; r < RPW; r++) {
            s1[r] += __shfl_down_sync(0xffffffffu, s1[r], off);
            s2[r] += __shfl_down_sync(0xffffffffu, s2[r], off);
        }
    }
    if (lane == 0) {
#pragma unroll
        for (int r = 0; r < RPW; r++) {
            g_x8[row0 + r] = s1[r] * 0.125f;
            g_y8[row0 + r] = s2[r] * 0.125f;
        }
    }
    pdl_trigger();   // data-complete trigger: sel_0 consumes y8
}

// K3(b): stable descending rank of y among valid columns for ONE batch.
// grid 64 blocks, 32 columns/block, 8 threads per column.
// Triggers at END (out_b directly consumes xm/ym/scale).
__global__ void __launch_bounds__(256) k_select(const int* __restrict__ n_src,
                                                const int* __restrict__ ns_tgt,
                                                int b) {
    pdl_wait();
    __shared__ __align__(16) float ys[N];
    int ns   = ns_tgt[b];
    int nsrc = n_src[b];
    int kb   = (int)((float)nsrc * 0.4f);   // float32 mul + trunc, matches ref

    const float4* src4 = reinterpret_cast<const float4*>(g_y8 + b * N);
    float4* ys4 = reinterpret_cast<float4*>(ys);
    for (int l = threadIdx.x; l < N / 4; l += 256)
        ys4[l] = src4[l];
    __syncthreads();

    int q  = threadIdx.x & 7;                 // 8 threads per column
    int jj = threadIdx.x >> 3;                // 0..31
    int j  = blockIdx.x * 32 + jj;
    float yj = ys[j];
    int cnt = 0;
#pragma unroll 4
    for (int l4 = q; l4 < N / 4; l4 += 8) {
        float4 v = ys4[l4];
        int l = l4 * 4;
        cnt += (l     < ns) && ((v.x > yj) || ((v.x == yj) && (l     < j)));
        cnt += (l + 1 < ns) && ((v.y > yj) || ((v.y == yj) && (l + 1 < j)));
        cnt += (l + 2 < ns) && ((v.z > yj) || ((v.z == yj) && (l + 2 < j)));
        cnt += (l + 3 < ns) && ((v.w > yj) || ((v.w == yj) && (l + 3 < j)));
    }
    cnt += __shfl_xor_sync(0xffffffffu, cnt, 1);
    cnt += __shfl_xor_sync(0xffffffffu, cnt, 2);
    cnt += __shfl_xor_sync(0xffffffffu, cnt, 4);

    if (q == 0) {
        bool act = (j < ns) && (cnt < kb) && (j < nsrc);
        float xj = g_x8[b * N + j];
        g_xm[b * N + j] = act ? xj : -1e30f;
        g_ym[b * N + j] = act ? yj : -1e30f;
    }
    if (blockIdx.x == 0 && threadIdx.x == 0)
        g_scale[b] = 1.0f / ((float)nsrc * 0.4f);
    pdl_trigger();   // data-complete trigger: out_b consumes xm/ym/scale
}

// K4(b): materialize output rows for ONE batch. 128 blocks x 16 rows.
// EARLY trigger: the successor (sel_{b+1}) consumes only xy data, which is
// from a fully-completed kernel by now -> safe to release it immediately.
__global__ void __launch_bounds__(256) k_out(float* __restrict__ out, int b) {
    pdl_wait();
    pdl_trigger();                   // release successor immediately
    int tile = blockIdx.x;           // 0..127
    int row0 = b * N + tile * TR;

    const float4* y4  = reinterpret_cast<const float4*>(g_y8 + b * N);
    const float4* xm4 = reinterpret_cast<const float4*>(g_xm + b * N);
    int t0 = threadIdx.x, t1 = threadIdx.x + 256;
    float4 yA  = y4[t0],  yB  = y4[t1];
    float4 xmA = xm4[t0], xmB = xm4[t1];
    float sc = g_scale[b];

    __shared__ float s_x[TR], s_ym[TR];
    if (threadIdx.x < TR)
        s_x[threadIdx.x] = g_x8[row0 + threadIdx.x];
    else if (threadIdx.x < 2 * TR)
        s_ym[threadIdx.x - TR] = g_ym[row0 + threadIdx.x - TR];
    __syncthreads();

#pragma unroll 4
    for (int r = 0; r < TR; r++) {
        float xi  = s_x[r];
        float ymi = s_ym[r];
        float4* o4 = reinterpret_cast<float4*>(out + (size_t)(row0 + r) * N);

        float4 rA, rB;
        {
            float e0 = xi + yA.x, e1 = xi + yA.y, e2 = xi + yA.z, e3 = xi + yA.w;
            rA.x = (fminf(e0, xmA.x + ymi) > 0.f) ? sc * tanh_fast(e0) : 0.f;
            rA.y = (fminf(e1, xmA.y + ymi) > 0.f) ? sc * tanh_fast(e1) : 0.f;
            rA.z = (fminf(e2, xmA.z + ymi) > 0.f) ? sc * tanh_fast(e2) : 0.f;
            rA.w = (fminf(e3, xmA.w + ymi) > 0.f) ? sc * tanh_fast(e3) : 0.f;
        }
        {
            float e0 = xi + yB.x, e1 = xi + yB.y, e2 = xi + yB.z, e3 = xi + yB.w;
            rB.x = (fminf(e0, xmB.x + ymi) > 0.f) ? sc * tanh_fast(e0) : 0.f;
            rB.y = (fminf(e1, xmB.y + ymi) > 0.f) ? sc * tanh_fast(e1) : 0.f;
            rB.z = (fminf(e2, xmB.z + ymi) > 0.f) ? sc * tanh_fast(e2) : 0.f;
            rB.w = (fminf(e3, xmB.w + ymi) > 0.f) ? sc * tanh_fast(e3) : 0.f;
        }
        __stcs(&o4[t0], rA);   // streaming store: output >> L2, evict-first
        __stcs(&o4[t1], rB);
    }
}

// Helper: launch with programmatic stream serialization (PDL)
template <typename... Args>
static void launch_pdl(void (*kernel)(Args...), dim3 grid, dim3 block,
                       cudaStream_t stream, Args... args) {
    cudaLaunchConfig_t cfg = {};
    cfg.gridDim = grid;
    cfg.blockDim = block;
    cfg.dynamicSmemBytes = 0;
    cfg.stream = stream;
    cudaLaunchAttribute attr[1];
    attr[0].id = cudaLaunchAttributeProgrammaticStreamSerialization;
    attr[0].val.programmaticStreamSerializationAllowed = 1;
    cfg.attrs = attr;
    cfg.numAttrs = 1;
    cudaLaunchKernelEx(&cfg, kernel, args...);
}

extern "C" void kernel_launch(void* const* d_in, const int* in_sizes, int n_in,
                              void* d_out, int out_size) {
    const float* emb1  = (const float*)d_in[0];
    const float* W     = (const float*)d_in[1];
    const float* a1    = (const float*)d_in[2];
    const float* a2    = (const float*)d_in[3];
    const int*   n_src = (const int*)d_in[4];
    const int*   nstgt = (const int*)d_in[5];
    float* out = (float*)d_out;
    cudaStream_t s = 0;  // capture stream (legacy default under graph capture)

    k_wproj<<<16, 256, 0, s>>>(W, a1, a2);
    launch_pdl(k_xy, dim3((B * N / RPW) / 8), dim3(256), s, emb1);
    // Per-batch cascade: sel_b (end-trigger) -> out_b (early-trigger) ->
    // sel_{b+1} ...  Out kernels pile up and run concurrently.
    for (int b = 0; b < B; b++) {
        launch_pdl(k_select, dim3(64), dim3(256), s, n_src, nstgt, b);
        launch_pdl(k_out, dim3(N / TR), dim3(256), s, out, b);
    }
}

// round 11
// speedup vs baseline: 3.2253x; 3.2253x over previous
#include <cuda_runtime.h>
#include <cstdint>

// Problem constants (fixed by the dataset)
#define B 8
#define N 2048
#define IN_F 512
#define OUT_F 128
#define RPW 2
#define TR 32

// Scratch (allocation-free rule: __device__ globals), 16B-aligned for float4
__device__ __align__(16) float g_w1[IN_F];
__device__ __align__(16) float g_w2[IN_F];
__device__ __align__(16) float g_x8[B * N];   // 0.125 * (emb1[b,i,:] . w1)
__device__ __align__(16) float g_y8[B * N];   // 0.125 * (emb1[b,i,:] . w2)
__device__ __align__(16) float g_xm[B * N];   // act ? x8 : -1e30
__device__ __align__(16) float g_ym[B * N];   // act ? y8 : -1e30
__device__ float g_scale[B];

__device__ __forceinline__ float tanh_fast(float x) {
    float r;
    asm("tanh.approx.f32 %0, %1;" : "=f"(r) : "f"(x));
    return r;
}

// PDL primitives. wait pairs with the immediately-preceding kernel's trigger.
__device__ __forceinline__ void pdl_wait() {
    asm volatile("griddepcontrol.wait;" ::: "memory");
}
__device__ __forceinline__ void pdl_trigger() {
    asm volatile("griddepcontrol.launch_dependents;" ::: "memory");
}

// K1: w1 = W^T a1, w2 = W^T a2.  W is [OUT_F, IN_F] row-major.
__global__ void __launch_bounds__(256) k_wproj(const float* __restrict__ W,
                                               const float* __restrict__ a1,
                                               const float* __restrict__ a2) {
    int lane = threadIdx.x & 31;
    int oq   = threadIdx.x >> 5;                 // 0..7
    int f    = blockIdx.x * 32 + lane;           // 0..511
    float s1 = 0.f, s2 = 0.f;
#pragma unroll
    for (int o = oq * 16; o < oq * 16 + 16; o++) {
        float w = __ldg(W + (size_t)o * IN_F + f);
        s1 = fmaf(w, __ldg(a1 + o), s1);
        s2 = fmaf(w, __ldg(a2 + o), s2);
    }
    __shared__ float p1[256], p2[256];
    p1[threadIdx.x] = s1;
    p2[threadIdx.x] = s2;
    __syncthreads();
    if (threadIdx.x < 32) {
        float r1 = 0.f, r2 = 0.f;
#pragma unroll
        for (int c = 0; c < 8; c++) {
            r1 += p1[lane + 32 * c];
            r2 += p2[lane + 32 * c];
        }
        g_w1[f] = r1;
        g_w2[f] = r2;
    }
    pdl_trigger();
}

// K2: per-warp dual dot products, 2 rows per warp (8 independent LDG.128 per
// lane in flight), w1/w2 held in registers. Stored pre-scaled by 0.125.
__global__ void __launch_bounds__(256) k_xy(const float* __restrict__ emb) {
    pdl_wait();
    int warp = (blockIdx.x * blockDim.x + threadIdx.x) >> 5;
    int lane = threadIdx.x & 31;
    int row0 = warp * RPW;                     // 8192 warps cover 16384 rows

    const float4* w1 = reinterpret_cast<const float4*>(g_w1);
    const float4* w2 = reinterpret_cast<const float4*>(g_w2);
    float4 W1[4], W2[4];
#pragma unroll
    for (int k = 0; k < 4; k++) {
        W1[k] = w1[lane + 32 * k];
        W2[k] = w2[lane + 32 * k];
    }

    float s1[RPW] = {0.f, 0.f}, s2[RPW] = {0.f, 0.f};
#pragma unroll
    for (int r = 0; r < RPW; r++) {
        const float4* row = reinterpret_cast<const float4*>(emb + (size_t)(row0 + r) * IN_F);
#pragma unroll
        for (int k = 0; k < 4; k++) {
            float4 e = row[lane + 32 * k];
            s1[r] = fmaf(e.x, W1[k].x, fmaf(e.y, W1[k].y, fmaf(e.z, W1[k].z, fmaf(e.w, W1[k].w, s1[r]))));
            s2[r] = fmaf(e.x, W2[k].x, fmaf(e.y, W2[k].y, fmaf(e.z, W2[k].z, fmaf(e.w, W2[k].w, s2[r]))));
        }
    }
#pragma unroll
    for (int off = 16; off; off >>= 1) {
#pragma unroll
        for (int r = 0; r < RPW; r++) {
            s1[r] += __shfl_down_sync(0xffffffffu, s1[r], off);
            s2[r] += __shfl_down_sync(0xffffffffu, s2[r], off);
        }
    }
    if (lane == 0) {
#pragma unroll
        for (int r = 0; r < RPW; r++) {
            g_x8[row0 + r] = s1[r] * 0.125f;
            g_y8[row0 + r] = s2[r] * 0.125f;
        }
    }
    pdl_trigger();
}

// K3: stable descending rank of y among valid columns; sentinel arrays.
// grid (N/32, B), block 256: 8 threads per column j, float4 smem scan.
__global__ void __launch_bounds__(256) k_select(const int* __restrict__ n_src,
                                                const int* __restrict__ ns_tgt) {
    pdl_wait();
    int b = blockIdx.y;
    __shared__ __align__(16) float ys[N];
    int ns   = ns_tgt[b];
    int nsrc = n_src[b];
    int kb   = (int)((float)nsrc * 0.4f);   // float32 mul + trunc, matches ref

    const float4* src4 = reinterpret_cast<const float4*>(g_y8 + b * N);
    float4* ys4 = reinterpret_cast<float4*>(ys);
    for (int l = threadIdx.x; l < N / 4; l += 256)
        ys4[l] = src4[l];
    __syncthreads();

    int q  = threadIdx.x & 7;                 // 8 threads per column
    int jj = threadIdx.x >> 3;                // 0..31
    int j  = blockIdx.x * 32 + jj;
    float yj = ys[j];
    int cnt = 0;
#pragma unroll 4
    for (int l4 = q; l4 < N / 4; l4 += 8) {
        float4 v = ys4[l4];
        int l = l4 * 4;
        cnt += (l     < ns) && ((v.x > yj) || ((v.x == yj) && (l     < j)));
        cnt += (l + 1 < ns) && ((v.y > yj) || ((v.y == yj) && (l + 1 < j)));
        cnt += (l + 2 < ns) && ((v.z > yj) || ((v.z == yj) && (l + 2 < j)));
        cnt += (l + 3 < ns) && ((v.w > yj) || ((v.w == yj) && (l + 3 < j)));
    }
    cnt += __shfl_xor_sync(0xffffffffu, cnt, 1);
    cnt += __shfl_xor_sync(0xffffffffu, cnt, 2);
    cnt += __shfl_xor_sync(0xffffffffu, cnt, 4);

    if (q == 0) {
        bool act = (j < ns) && (cnt < kb) && (j < nsrc);
        float xj = g_x8[b * N + j];
        g_xm[b * N + j] = act ? xj : -1e30f;
        g_ym[b * N + j] = act ? yj : -1e30f;
    }
    if (blockIdx.x == 0 && threadIdx.x == 0)
        g_scale[b] = 1.0f / ((float)nsrc * 0.4f);
    pdl_trigger();
}

// K4: materialize output. One block per 32 rows (512 blocks, single wave);
// per-thread column data (ym, xm for its 8 columns) lives in registers and
// is reused across all 32 rows. Symmetric formulation:
//   out[i,j] = (min(xm_j+ym_i, xm_i+ym_j) > 0) ? sc * tanh(xm_i + ym_j) : 0
// (sentinels make both conditions false when either endpoint is inactive;
//  when both active, xm_i = x_i and ym_j = y_j, so value matches reference)
__global__ void __launch_bounds__(256) k_out(float* __restrict__ out) {
    pdl_wait();
    int b    = blockIdx.x >> 6;      // N/TR = 64 tiles per batch
    int tile = blockIdx.x & 63;
    int row0 = b * N + tile * TR;

    const float4* ym4 = reinterpret_cast<const float4*>(g_ym + b * N);
    const float4* xm4 = reinterpret_cast<const float4*>(g_xm + b * N);
    int t0 = threadIdx.x, t1 = threadIdx.x + 256;
    float4 ymA = ym4[t0], ymB = ym4[t1];
    float4 xmA = xm4[t0], xmB = xm4[t1];
    float sc = g_scale[b];

    __shared__ float s_xm[TR], s_ym[TR];
    if (threadIdx.x < TR)
        s_xm[threadIdx.x] = g_xm[row0 + threadIdx.x];
    else if (threadIdx.x < 2 * TR)
        s_ym[threadIdx.x - TR] = g_ym[row0 + threadIdx.x - TR];
    __syncthreads();

#pragma unroll 4
    for (int r = 0; r < TR; r++) {
        float xmi = s_xm[r];
        float ymi = s_ym[r];
        float4* o4 = reinterpret_cast<float4*>(out + (size_t)(row0 + r) * N);

        float4 rA, rB;
        {
            float e0 = xmi + ymA.x, e1 = xmi + ymA.y, e2 = xmi + ymA.z, e3 = xmi + ymA.w;
            rA.x = (fminf(e0, xmA.x + ymi) > 0.f) ? sc * tanh_fast(e0) : 0.f;
            rA.y = (fminf(e1, xmA.y + ymi) > 0.f) ? sc * tanh_fast(e1) : 0.f;
            rA.z = (fminf(e2, xmA.z + ymi) > 0.f) ? sc * tanh_fast(e2) : 0.f;
            rA.w = (fminf(e3, xmA.w + ymi) > 0.f) ? sc * tanh_fast(e3) : 0.f;
        }
        {
            float e0 = xmi + ymB.x, e1 = xmi + ymB.y, e2 = xmi + ymB.z, e3 = xmi + ymB.w;
            rB.x = (fminf(e0, xmB.x + ymi) > 0.f) ? sc * tanh_fast(e0) : 0.f;
            rB.y = (fminf(e1, xmB.y + ymi) > 0.f) ? sc * tanh_fast(e1) : 0.f;
            rB.z = (fminf(e2, xmB.z + ymi) > 0.f) ? sc * tanh_fast(e2) : 0.f;
            rB.w = (fminf(e3, xmB.w + ymi) > 0.f) ? sc * tanh_fast(e3) : 0.f;
        }
        __stcs(&o4[t0], rA);   // streaming store: output >> L2, evict-first
        __stcs(&o4[t1], rB);
    }
}

// Helper: launch with programmatic stream serialization (PDL)
template <typename... Args>
static void launch_pdl(void (*kernel)(Args...), dim3 grid, dim3 block,
                       cudaStream_t stream, Args... args) {
    cudaLaunchConfig_t cfg = {};
    cfg.gridDim = grid;
    cfg.blockDim = block;
    cfg.dynamicSmemBytes = 0;
    cfg.stream = stream;
    cudaLaunchAttribute attr[1];
    attr[0].id = cudaLaunchAttributeProgrammaticStreamSerialization;
    attr[0].val.programmaticStreamSerializationAllowed = 1;
    cfg.attrs = attr;
    cfg.numAttrs = 1;
    cudaLaunchKernelEx(&cfg, kernel, args...);
}

extern "C" void kernel_launch(void* const* d_in, const int* in_sizes, int n_in,
                              void* d_out, int out_size) {
    const float* emb1  = (const float*)d_in[0];
    const float* W     = (const float*)d_in[1];
    const float* a1    = (const float*)d_in[2];
    const float* a2    = (const float*)d_in[3];
    const int*   n_src = (const int*)d_in[4];
    const int*   nstgt = (const int*)d_in[5];
    float* out = (float*)d_out;
    cudaStream_t s = 0;  // capture stream (legacy default under graph capture)

    k_wproj<<<16, 256, 0, s>>>(W, a1, a2);
    launch_pdl(k_xy, dim3((B * N / RPW) / 8), dim3(256), s, emb1);
    launch_pdl(k_select, dim3(N / 32, B), dim3(256), s, n_src, nstgt);
    launch_pdl(k_out, dim3(B * (N / TR)), dim3(256), s, out);
}

// round 12
// speedup vs baseline: 3.3200x; 1.0294x over previous
#include <cuda_runtime.h>
#include <cstdint>

// Problem constants (fixed by the dataset)
#define B 8
#define N 2048
#define IN_F 512
#define OUT_F 128
#define RPW 2
#define TR 16

// Scratch (allocation-free rule: __device__ globals), 16B-aligned for float4
__device__ __align__(16) float g_w1[IN_F];
__device__ __align__(16) float g_w2[IN_F];
__device__ __align__(16) float g_x8[B * N];   // 0.125 * (emb1[b,i,:] . w1)
__device__ __align__(16) float g_y8[B * N];   // 0.125 * (emb1[b,i,:] . w2)
__device__ __align__(16) float g_xm[B * N];   // act ? x8 : -1e30
__device__ __align__(16) float g_ym[B * N];   // act ? y8 : -1e30
__device__ float g_scale[B];

__device__ __forceinline__ float tanh_fast(float x) {
    float r;
    asm("tanh.approx.f32 %0, %1;" : "=f"(r) : "f"(x));
    return r;
}

// PDL primitives. wait gates only the PREDECESSOR's data; independent loads
// may be issued before it (prologue pattern).
__device__ __forceinline__ void pdl_wait() {
    asm volatile("griddepcontrol.wait;" ::: "memory");
}
__device__ __forceinline__ void pdl_trigger() {
    asm volatile("griddepcontrol.launch_dependents;" ::: "memory");
}

// K1: w1 = W^T a1, w2 = W^T a2.  W is [OUT_F, IN_F] row-major.
__global__ void __launch_bounds__(256) k_wproj(const float* __restrict__ W,
                                               const float* __restrict__ a1,
                                               const float* __restrict__ a2) {
    int lane = threadIdx.x & 31;
    int oq   = threadIdx.x >> 5;                 // 0..7
    int f    = blockIdx.x * 32 + lane;           // 0..511
    float s1 = 0.f, s2 = 0.f;
#pragma unroll
    for (int o = oq * 16; o < oq * 16 + 16; o++) {
        float w = __ldg(W + (size_t)o * IN_F + f);
        s1 = fmaf(w, __ldg(a1 + o), s1);
        s2 = fmaf(w, __ldg(a2 + o), s2);
    }
    __shared__ float p1[256], p2[256];
    p1[threadIdx.x] = s1;
    p2[threadIdx.x] = s2;
    __syncthreads();
    if (threadIdx.x < 32) {
        float r1 = 0.f, r2 = 0.f;
#pragma unroll
        for (int c = 0; c < 8; c++) {
            r1 += p1[lane + 32 * c];
            r2 += p2[lane + 32 * c];
        }
        g_w1[f] = r1;
        g_w2[f] = r2;
    }
    pdl_trigger();
}

// K2: per-warp dual dot products, 2 rows per warp. PDL prologue: row 0's emb
// loads (independent of wproj) are issued BEFORE the wait so they stream
// during wproj's tail. w1/w2 read after the wait.
__global__ void __launch_bounds__(256) k_xy(const float* __restrict__ emb) {
    int warp = (blockIdx.x * blockDim.x + threadIdx.x) >> 5;
    int lane = threadIdx.x & 31;
    int row0 = warp * RPW;                     // 8192 warps cover 16384 rows

    // ── prologue: independent emb loads for row 0 (4 x LDG.128 in flight)
    const float4* rowp0 = reinterpret_cast<const float4*>(emb + (size_t)row0 * IN_F);
    float4 e0[4];
#pragma unroll
    for (int k = 0; k < 4; k++) e0[k] = rowp0[lane + 32 * k];

    pdl_wait();   // w1/w2 now visible

    const float4* w1 = reinterpret_cast<const float4*>(g_w1);
    const float4* w2 = reinterpret_cast<const float4*>(g_w2);
    float4 W1[4], W2[4];
#pragma unroll
    for (int k = 0; k < 4; k++) {
        W1[k] = w1[lane + 32 * k];
        W2[k] = w2[lane + 32 * k];
    }

    float s1[RPW] = {0.f, 0.f}, s2[RPW] = {0.f, 0.f};
#pragma unroll
    for (int k = 0; k < 4; k++) {
        s1[0] = fmaf(e0[k].x, W1[k].x, fmaf(e0[k].y, W1[k].y, fmaf(e0[k].z, W1[k].z, fmaf(e0[k].w, W1[k].w, s1[0]))));
        s2[0] = fmaf(e0[k].x, W2[k].x, fmaf(e0[k].y, W2[k].y, fmaf(e0[k].z, W2[k].z, fmaf(e0[k].w, W2[k].w, s2[0]))));
    }
    {
        const float4* rowp1 = reinterpret_cast<const float4*>(emb + (size_t)(row0 + 1) * IN_F);
#pragma unroll
        for (int k = 0; k < 4; k++) {
            float4 e = rowp1[lane + 32 * k];
            s1[1] = fmaf(e.x, W1[k].x, fmaf(e.y, W1[k].y, fmaf(e.z, W1[k].z, fmaf(e.w, W1[k].w, s1[1]))));
            s2[1] = fmaf(e.x, W2[k].x, fmaf(e.y, W2[k].y, fmaf(e.z, W2[k].z, fmaf(e.w, W2[k].w, s2[1]))));
        }
    }
#pragma unroll
    for (int off = 16; off; off >>= 1) {
#pragma unroll
        for (int r = 0; r < RPW; r++) {
            s1[r] += __shfl_down_sync(0xffffffffu, s1[r], off);
            s2[r] += __shfl_down_sync(0xffffffffu, s2[r], off);
        }
    }
    if (lane == 0) {
#pragma unroll
        for (int r = 0; r < RPW; r++) {
            g_x8[row0 + r] = s1[r] * 0.125f;
            g_y8[row0 + r] = s2[r] * 0.125f;
        }
    }
    pdl_trigger();
}

// K3: stable descending rank of y among valid columns; sentinel arrays.
// grid (N/32, B), block 256: 8 threads per column j, float4 smem scan.
// PDL prologue: n_src/ns_tgt loads are input-only, issued before the wait.
__global__ void __launch_bounds__(256) k_select(const int* __restrict__ n_src,
                                                const int* __restrict__ ns_tgt) {
    int b = blockIdx.y;
    int ns   = ns_tgt[b];                     // independent of predecessor
    int nsrc = n_src[b];
    int kb   = (int)((float)nsrc * 0.4f);     // fp32 mul + trunc, matches ref

    pdl_wait();   // y8/x8 now visible

    __shared__ __align__(16) float ys[N];
    const float4* src4 = reinterpret_cast<const float4*>(g_y8 + b * N);
    float4* ys4 = reinterpret_cast<float4*>(ys);
    for (int l = threadIdx.x; l < N / 4; l += 256)
        ys4[l] = src4[l];
    __syncthreads();

    int q  = threadIdx.x & 7;                 // 8 threads per column
    int jj = threadIdx.x >> 3;                // 0..31
    int j  = blockIdx.x * 32 + jj;
    float yj = ys[j];
    int cnt = 0;
#pragma unroll 4
    for (int l4 = q; l4 < N / 4; l4 += 8) {
        float4 v = ys4[l4];
        int l = l4 * 4;
        cnt += (l     < ns) && ((v.x > yj) || ((v.x == yj) && (l     < j)));
        cnt += (l + 1 < ns) && ((v.y > yj) || ((v.y == yj) && (l + 1 < j)));
        cnt += (l + 2 < ns) && ((v.z > yj) || ((v.z == yj) && (l + 2 < j)));
        cnt += (l + 3 < ns) && ((v.w > yj) || ((v.w == yj) && (l + 3 < j)));
    }
    cnt += __shfl_xor_sync(0xffffffffu, cnt, 1);
    cnt += __shfl_xor_sync(0xffffffffu, cnt, 2);
    cnt += __shfl_xor_sync(0xffffffffu, cnt, 4);

    if (q == 0) {
        bool act = (j < ns) && (cnt < kb) && (j < nsrc);
        float xj = g_x8[b * N + j];
        g_xm[b * N + j] = act ? xj : -1e30f;
        g_ym[b * N + j] = act ? yj : -1e30f;
    }
    if (blockIdx.x == 0 && threadIdx.x == 0)
        g_scale[b] = 1.0f / ((float)nsrc * 0.4f);
    pdl_trigger();
}

// K4: materialize output. One block per 16 rows (grid 1024, ~7 blocks/SM).
// PDL prologue: y8/x8 come from k_xy (two kernels back, fully complete and
// flushed before this kernel could launch) -> loaded BEFORE the wait, hiding
// the block ramp under k_select's execution. xm/ym/scale (sel outputs) are
// read only after the wait.
__global__ void __launch_bounds__(256) k_out(float* __restrict__ out) {
    int b    = blockIdx.x >> 7;      // N/TR = 128 tiles per batch
    int tile = blockIdx.x & 127;
    int row0 = b * N + tile * TR;
    int t0 = threadIdx.x, t1 = threadIdx.x + 256;

    // ── prologue: xy-era data, independent of predecessor (k_select)
    const float4* y4 = reinterpret_cast<const float4*>(g_y8 + b * N);
    float4 yA = y4[t0], yB = y4[t1];
    __shared__ float s_x[TR], s_ym[TR];
    if (threadIdx.x < TR)
        s_x[threadIdx.x] = g_x8[row0 + threadIdx.x];

    pdl_wait();   // xm/ym/scale now visible

    const float4* xm4 = reinterpret_cast<const float4*>(g_xm + b * N);
    float4 xmA = xm4[t0], xmB = xm4[t1];
    float sc = g_scale[b];
    if (threadIdx.x >= TR && threadIdx.x < 2 * TR)
        s_ym[threadIdx.x - TR] = g_ym[row0 + threadIdx.x - TR];
    __syncthreads();

#pragma unroll 4
    for (int r = 0; r < TR; r++) {
        float xi  = s_x[r];
        float ymi = s_ym[r];
        float4* o4 = reinterpret_cast<float4*>(out + (size_t)(row0 + r) * N);

        float4 rA, rB;
        {
            float e0 = xi + yA.x, e1 = xi + yA.y, e2 = xi + yA.z, e3 = xi + yA.w;
            rA.x = (fminf(e0, xmA.x + ymi) > 0.f) ? sc * tanh_fast(e0) : 0.f;
            rA.y = (fminf(e1, xmA.y + ymi) > 0.f) ? sc * tanh_fast(e1) : 0.f;
            rA.z = (fminf(e2, xmA.z + ymi) > 0.f) ? sc * tanh_fast(e2) : 0.f;
            rA.w = (fminf(e3, xmA.w + ymi) > 0.f) ? sc * tanh_fast(e3) : 0.f;
        }
        {
            float e0 = xi + yB.x, e1 = xi + yB.y, e2 = xi + yB.z, e3 = xi + yB.w;
            rB.x = (fminf(e0, xmB.x + ymi) > 0.f) ? sc * tanh_fast(e0) : 0.f;
            rB.y = (fminf(e1, xmB.y + ymi) > 0.f) ? sc * tanh_fast(e1) : 0.f;
            rB.z = (fminf(e2, xmB.z + ymi) > 0.f) ? sc * tanh_fast(e2) : 0.f;
            rB.w = (fminf(e3, xmB.w + ymi) > 0.f) ? sc * tanh_fast(e3) : 0.f;
        }
        __stcs(&o4[t0], rA);   // streaming store: output >> L2, evict-first
        __stcs(&o4[t1], rB);
    }
}

// Helper: launch with programmatic stream serialization (PDL)
template <typename... Args>
static void launch_pdl(void (*kernel)(Args...), dim3 grid, dim3 block,
                       cudaStream_t stream, Args... args) {
    cudaLaunchConfig_t cfg = {};
    cfg.gridDim = grid;
    cfg.blockDim = block;
    cfg.dynamicSmemBytes = 0;
    cfg.stream = stream;
    cudaLaunchAttribute attr[1];
    attr[0].id = cudaLaunchAttributeProgrammaticStreamSerialization;
    attr[0].val.programmaticStreamSerializationAllowed = 1;
    cfg.attrs = attr;
    cfg.numAttrs = 1;
    cudaLaunchKernelEx(&cfg, kernel, args...);
}

extern "C" void kernel_launch(void* const* d_in, const int* in_sizes, int n_in,
                              void* d_out, int out_size) {
    const float* emb1  = (const float*)d_in[0];
    const float* W     = (const float*)d_in[1];
    const float* a1    = (const float*)d_in[2];
    const float* a2    = (const float*)d_in[3];
    const int*   n_src = (const int*)d_in[4];
    const int*   nstgt = (const int*)d_in[5];
    float* out = (float*)d_out;
    cudaStream_t s = 0;  // capture stream (legacy default under graph capture)

    k_wproj<<<16, 256, 0, s>>>(W, a1, a2);
    launch_pdl(k_xy, dim3((B * N / RPW) / 8), dim3(256), s, emb1);
    launch_pdl(k_select, dim3(N / 32, B), dim3(256), s, n_src, nstgt);
    launch_pdl(k_out, dim3(B * (N / TR)), dim3(256), s, out);
}